// round 1
// baseline (speedup 1.0000x reference)
#include <cuda_runtime.h>
#include <cuda_bf16.h>
#include <cstdint>

#define NUM_USERS 100000
#define NUM_ITEMS 50000
#define EMB_DIM   64
#define N_NODES   (NUM_USERS + NUM_ITEMS)   // 150000
#define N_EDGES   4000000
#define BATCH     4096
#define NFLOAT    (N_NODES * EMB_DIM)        // 9,600,000
#define NV4       (NFLOAT / 4)               // 2,400,000

// Scratch (device-global; no runtime allocation allowed)
__device__ float g_acc[NFLOAT];
__device__ float g_bufA[NFLOAT];
__device__ float g_bufB[NFLOAT];

// ---------------------------------------------------------------------------
// Init: acc = concat(user_emb,item_emb); bufA = same; bufB = 0
// ---------------------------------------------------------------------------
__global__ void init_kernel(const float* __restrict__ user_emb,
                            const float* __restrict__ item_emb) {
    int i = blockIdx.x * blockDim.x + threadIdx.x;   // float4 index
    if (i >= NV4) return;
    int node = i >> 4;                               // 16 float4 per node
    float4 v;
    if (node < NUM_USERS) {
        v = ((const float4*)user_emb)[i];
    } else {
        v = ((const float4*)item_emb)[i - NUM_USERS * (EMB_DIM / 4)];
    }
    ((float4*)g_acc)[i]  = v;
    ((float4*)g_bufA)[i] = v;
    ((float4*)g_bufB)[i] = make_float4(0.f, 0.f, 0.f, 0.f);
}

// ---------------------------------------------------------------------------
// SpMM: y[row[e]] += vals[e] * x[col[e]]   (y must be pre-zeroed)
// 16 threads per edge, one float4 each, vector reduction atomics.
// ---------------------------------------------------------------------------
__global__ void spmm_kernel(const float* __restrict__ x,
                            float* __restrict__ y,
                            const float* __restrict__ vals,
                            const int* __restrict__ row,
                            const int* __restrict__ col) {
    long long t = (long long)blockIdx.x * blockDim.x + threadIdx.x;
    long long e = t >> 4;
    if (e >= N_EDGES) return;
    int chunk = (int)(t & 15);

    int c   = col[e];
    int r   = row[e];
    float v = vals[e];

    float4 xv = ((const float4*)(x + (size_t)c * EMB_DIM))[chunk];
    float a = xv.x * v, b = xv.y * v, cc = xv.z * v, d = xv.w * v;

    float* p = y + (size_t)r * EMB_DIM + chunk * 4;
    asm volatile("red.global.add.v4.f32 [%0], {%1,%2,%3,%4};"
                 :: "l"(p), "f"(a), "f"(b), "f"(cc), "f"(d)
                 : "memory");
}

// ---------------------------------------------------------------------------
// Fuse: acc += src; optionally zero another buffer (next layer's destination)
// ---------------------------------------------------------------------------
__global__ void fuse_kernel(const float* __restrict__ src,
                            float* __restrict__ zero_buf /* may be null */) {
    int i = blockIdx.x * blockDim.x + threadIdx.x;
    if (i >= NV4) return;
    float4 a = ((const float4*)g_acc)[i];
    float4 s = ((const float4*)src)[i];
    a.x += s.x; a.y += s.y; a.z += s.z; a.w += s.w;
    ((float4*)g_acc)[i] = a;
    if (zero_buf) {
        ((float4*)zero_buf)[i] = make_float4(0.f, 0.f, 0.f, 0.f);
    }
}

// ---------------------------------------------------------------------------
// Scoring: one warp per batch element.
// light_out = acc/4 ; score = dot(acc_u, acc_i) / 16
// out layout: [pos_scores(4096) | neg_scores(4096)]
// ---------------------------------------------------------------------------
__global__ void score_kernel(const int* __restrict__ users,
                             const int* __restrict__ pos_items,
                             const int* __restrict__ neg_items,
                             float* __restrict__ out) {
    int warp = (blockIdx.x * blockDim.x + threadIdx.x) >> 5;
    int lane = threadIdx.x & 31;
    if (warp >= BATCH) return;

    int u = users[warp];
    int p = pos_items[warp] + NUM_USERS;
    int n = neg_items[warp] + NUM_USERS;

    const float2* A = (const float2*)g_acc;
    float2 ue = A[(size_t)u * 32 + lane];
    float2 pe = A[(size_t)p * 32 + lane];
    float2 ne = A[(size_t)n * 32 + lane];

    float ps = ue.x * pe.x + ue.y * pe.y;
    float ns = ue.x * ne.x + ue.y * ne.y;
    #pragma unroll
    for (int o = 16; o > 0; o >>= 1) {
        ps += __shfl_down_sync(0xFFFFFFFFu, ps, o);
        ns += __shfl_down_sync(0xFFFFFFFFu, ns, o);
    }
    if (lane == 0) {
        out[warp]         = ps * (1.0f / 16.0f);
        out[BATCH + warp] = ns * (1.0f / 16.0f);
    }
}

// ---------------------------------------------------------------------------
extern "C" void kernel_launch(void* const* d_in, const int* in_sizes, int n_in,
                              void* d_out, int out_size) {
    const float* user_emb  = (const float*)d_in[0];
    const float* item_emb  = (const float*)d_in[1];
    const float* vals      = (const float*)d_in[2];
    const int*   row       = (const int*)d_in[3];
    const int*   col       = (const int*)d_in[4];
    const int*   users     = (const int*)d_in[5];
    const int*   pos_items = (const int*)d_in[6];
    const int*   neg_items = (const int*)d_in[7];
    float* out = (float*)d_out;

    float* accP; cudaGetSymbolAddress((void**)&accP, g_acc);
    float* aP;   cudaGetSymbolAddress((void**)&aP,   g_bufA);
    float* bP;   cudaGetSymbolAddress((void**)&bP,   g_bufB);

    const int TB = 256;
    const int initBlocks = (NV4 + TB - 1) / TB;
    const long long spmmThreads = (long long)N_EDGES * 16;
    const int spmmBlocks = (int)((spmmThreads + TB - 1) / TB);

    // acc = x = concat ; B = 0
    init_kernel<<<initBlocks, TB>>>(user_emb, item_emb);

    // Layer 1: A -> B ; acc += B ; zero A
    spmm_kernel<<<spmmBlocks, TB>>>(aP, bP, vals, row, col);
    fuse_kernel<<<initBlocks, TB>>>(bP, aP);

    // Layer 2: B -> A ; acc += A ; zero B
    spmm_kernel<<<spmmBlocks, TB>>>(bP, aP, vals, row, col);
    fuse_kernel<<<initBlocks, TB>>>(aP, bP);

    // Layer 3: A -> B ; acc += B
    spmm_kernel<<<spmmBlocks, TB>>>(aP, bP, vals, row, col);
    fuse_kernel<<<initBlocks, TB>>>(bP, nullptr);

    // Scores
    score_kernel<<<(BATCH * 32) / TB, TB>>>(users, pos_items, neg_items, out);
}

// round 2
// speedup vs baseline: 1.4351x; 1.4351x over previous
#include <cuda_runtime.h>
#include <cuda_bf16.h>
#include <cstdint>

#define NUM_USERS 100000
#define NUM_ITEMS 50000
#define EMB_DIM   64
#define N_NODES   (NUM_USERS + NUM_ITEMS)   // 150000
#define N_EDGES   4000000
#define BATCH     4096
#define NFLOAT    (N_NODES * EMB_DIM)        // 9,600,000
#define NV4       (NFLOAT / 4)               // 2,400,000

// Layer outputs (device-global scratch; no runtime allocation allowed)
__device__ float g_x1[NFLOAT];
__device__ float g_x2[NFLOAT];
__device__ float g_x3[NFLOAT];

// ---------------------------------------------------------------------------
// Zero the three layer-output buffers.
// ---------------------------------------------------------------------------
__global__ void zero3_kernel() {
    int i = blockIdx.x * blockDim.x + threadIdx.x;
    if (i >= NV4) return;
    float4 z = make_float4(0.f, 0.f, 0.f, 0.f);
    ((float4*)g_x1)[i] = z;
    ((float4*)g_x2)[i] = z;
    ((float4*)g_x3)[i] = z;
}

// ---------------------------------------------------------------------------
// SpMM: y[row[e]] += vals[e] * x[col[e]]   (y pre-zeroed)
// One warp owns 32 edges: metadata loaded coalesced once, shfl-broadcast.
// Each edge handled by 16 lanes (one float4 each); 4 edge-pairs in flight.
// FIRST=true reads x0 from the two input embedding tables (concat semantics).
// ---------------------------------------------------------------------------
template<bool FIRST>
__global__ void __launch_bounds__(256)
spmm_kernel(const float* __restrict__ x,
            const float* __restrict__ user_emb,
            const float* __restrict__ item_emb,
            float* __restrict__ y,
            const float* __restrict__ vals,
            const int* __restrict__ row,
            const int* __restrict__ col) {
    const unsigned FULL = 0xFFFFFFFFu;
    int warpId = (blockIdx.x * blockDim.x + threadIdx.x) >> 5;
    int lane   = threadIdx.x & 31;
    int base   = warpId * 32;          // 4M edges / 32 per warp, exact

    // Coalesced metadata for this warp's 32 edges
    int   c = col[base + lane];
    int   r = row[base + lane];
    float v = vals[base + lane];

    int half  = lane >> 4;             // which edge of the pair
    int chunk = lane & 15;             // float4 index within the 64-float row

    #pragma unroll
    for (int kk = 0; kk < 4; kk++) {
        int cc[4], rr[4];
        float vv[4];
        #pragma unroll
        for (int j = 0; j < 4; j++) {
            int s = (kk * 4 + j) * 2 + half;    // source edge lane
            cc[j] = __shfl_sync(FULL, c, s);
            rr[j] = __shfl_sync(FULL, r, s);
            vv[j] = __shfl_sync(FULL, v, s);
        }
        float4 xv[4];
        #pragma unroll
        for (int j = 0; j < 4; j++) {
            if (FIRST) {
                const float4* xp = (cc[j] < NUM_USERS)
                    ? (const float4*)user_emb + (size_t)cc[j] * 16
                    : (const float4*)item_emb + (size_t)(cc[j] - NUM_USERS) * 16;
                xv[j] = xp[chunk];
            } else {
                xv[j] = ((const float4*)x)[(size_t)cc[j] * 16 + chunk];
            }
        }
        #pragma unroll
        for (int j = 0; j < 4; j++) {
            float a = xv[j].x * vv[j];
            float b = xv[j].y * vv[j];
            float cgm = xv[j].z * vv[j];
            float d = xv[j].w * vv[j];
            float* p = y + (size_t)rr[j] * EMB_DIM + chunk * 4;
            asm volatile("red.global.add.v4.f32 [%0], {%1,%2,%3,%4};"
                         :: "l"(p), "f"(a), "f"(b), "f"(cgm), "f"(d)
                         : "memory");
        }
    }
}

// ---------------------------------------------------------------------------
// Scoring: one warp per batch element.
// acc = x0 + x1 + x2 + x3 (x0 from input tables); score = dot(acc_u,acc_i)/16
// out layout: [pos_scores(4096) | neg_scores(4096)]
// ---------------------------------------------------------------------------
__global__ void score_kernel(const float* __restrict__ user_emb,
                             const float* __restrict__ item_emb,
                             const int* __restrict__ users,
                             const int* __restrict__ pos_items,
                             const int* __restrict__ neg_items,
                             float* __restrict__ out) {
    int warp = (blockIdx.x * blockDim.x + threadIdx.x) >> 5;
    int lane = threadIdx.x & 31;
    if (warp >= BATCH) return;

    int u  = users[warp];
    int pi = pos_items[warp];
    int ni = neg_items[warp];

    const float2* UE = (const float2*)user_emb;
    const float2* IE = (const float2*)item_emb;
    const float2* X1 = (const float2*)g_x1;
    const float2* X2 = (const float2*)g_x2;
    const float2* X3 = (const float2*)g_x3;

    size_t un = (size_t)u * 32 + lane;
    size_t pn = (size_t)(NUM_USERS + pi) * 32 + lane;
    size_t nn = (size_t)(NUM_USERS + ni) * 32 + lane;
    size_t pl = (size_t)pi * 32 + lane;
    size_t nl = (size_t)ni * 32 + lane;

    float2 a, t;
    // user acc
    a = UE[un];
    t = X1[un]; a.x += t.x; a.y += t.y;
    t = X2[un]; a.x += t.x; a.y += t.y;
    t = X3[un]; a.x += t.x; a.y += t.y;
    float2 uacc = a;
    // pos item acc
    a = IE[pl];
    t = X1[pn]; a.x += t.x; a.y += t.y;
    t = X2[pn]; a.x += t.x; a.y += t.y;
    t = X3[pn]; a.x += t.x; a.y += t.y;
    float2 pacc = a;
    // neg item acc
    a = IE[nl];
    t = X1[nn]; a.x += t.x; a.y += t.y;
    t = X2[nn]; a.x += t.x; a.y += t.y;
    t = X3[nn]; a.x += t.x; a.y += t.y;
    float2 nacc = a;

    float ps = uacc.x * pacc.x + uacc.y * pacc.y;
    float ns = uacc.x * nacc.x + uacc.y * nacc.y;
    #pragma unroll
    for (int o = 16; o > 0; o >>= 1) {
        ps += __shfl_down_sync(0xFFFFFFFFu, ps, o);
        ns += __shfl_down_sync(0xFFFFFFFFu, ns, o);
    }
    if (lane == 0) {
        out[warp]         = ps * (1.0f / 16.0f);
        out[BATCH + warp] = ns * (1.0f / 16.0f);
    }
}

// ---------------------------------------------------------------------------
extern "C" void kernel_launch(void* const* d_in, const int* in_sizes, int n_in,
                              void* d_out, int out_size) {
    const float* user_emb  = (const float*)d_in[0];
    const float* item_emb  = (const float*)d_in[1];
    const float* vals      = (const float*)d_in[2];
    const int*   row       = (const int*)d_in[3];
    const int*   col       = (const int*)d_in[4];
    const int*   users     = (const int*)d_in[5];
    const int*   pos_items = (const int*)d_in[6];
    const int*   neg_items = (const int*)d_in[7];
    float* out = (float*)d_out;

    float* x1P; cudaGetSymbolAddress((void**)&x1P, g_x1);
    float* x2P; cudaGetSymbolAddress((void**)&x2P, g_x2);
    float* x3P; cudaGetSymbolAddress((void**)&x3P, g_x3);

    const int TB = 256;
    const int zeroBlocks = (NV4 + TB - 1) / TB;
    // one warp per 32 edges
    const int spmmBlocks = (N_EDGES / 32) * 32 / TB;   // 125000 warps -> 15625 blocks

    zero3_kernel<<<zeroBlocks, TB>>>();

    // Layer 1: x0 (inputs) -> x1
    spmm_kernel<true><<<spmmBlocks, TB>>>(nullptr, user_emb, item_emb, x1P,
                                          vals, row, col);
    // Layer 2: x1 -> x2
    spmm_kernel<false><<<spmmBlocks, TB>>>(x1P, nullptr, nullptr, x2P,
                                           vals, row, col);
    // Layer 3: x2 -> x3
    spmm_kernel<false><<<spmmBlocks, TB>>>(x2P, nullptr, nullptr, x3P,
                                           vals, row, col);

    score_kernel<<<(BATCH * 32) / TB, TB>>>(user_emb, item_emb,
                                            users, pos_items, neg_items, out);
}

// round 3
// speedup vs baseline: 1.8951x; 1.3205x over previous
#include <cuda_runtime.h>
#include <cuda_bf16.h>
#include <cstdint>

#define NUM_USERS 100000
#define NUM_ITEMS 50000
#define EMB_DIM   64
#define N_NODES   (NUM_USERS + NUM_ITEMS)   // 150000
#define N_EDGES   4000000
#define BATCH     4096
#define NFLOAT    (N_NODES * EMB_DIM)        // 9,600,000
#define NV4       (NFLOAT / 4)               // 2,400,000

// Layer outputs + needed-node flags (device-global scratch)
__device__ float g_x1[NFLOAT];
__device__ float g_x2[NFLOAT];
__device__ float g_x3[NFLOAT];
__device__ int   g_flag[N_NODES];

// ---------------------------------------------------------------------------
// Zero the three layer-output buffers + flags.
// ---------------------------------------------------------------------------
__global__ void zero_kernel() {
    int i = blockIdx.x * blockDim.x + threadIdx.x;
    if (i < NV4) {
        float4 z = make_float4(0.f, 0.f, 0.f, 0.f);
        ((float4*)g_x1)[i] = z;
        ((float4*)g_x2)[i] = z;
        ((float4*)g_x3)[i] = z;
    }
    if (i < N_NODES) g_flag[i] = 0;
}

// ---------------------------------------------------------------------------
// Mark nodes whose final (layer-3) output is actually consumed by scoring.
// ---------------------------------------------------------------------------
__global__ void mark_kernel(const int* __restrict__ users,
                            const int* __restrict__ pos_items,
                            const int* __restrict__ neg_items) {
    int i = blockIdx.x * blockDim.x + threadIdx.x;
    if (i >= BATCH) return;
    g_flag[users[i]]                 = 1;
    g_flag[NUM_USERS + pos_items[i]] = 1;
    g_flag[NUM_USERS + neg_items[i]] = 1;
}

// ---------------------------------------------------------------------------
// Full SpMM: y[row[e]] += vals[e] * x[col[e]]   (y pre-zeroed)
// One warp owns 32 edges: metadata loaded coalesced, shfl-broadcast.
// Each edge handled by 16 lanes (one float4 each); 4 edge-pairs in flight.
// FIRST=true reads x0 from the two input embedding tables (concat semantics).
// ---------------------------------------------------------------------------
template<bool FIRST>
__global__ void __launch_bounds__(256)
spmm_kernel(const float* __restrict__ x,
            const float* __restrict__ user_emb,
            const float* __restrict__ item_emb,
            float* __restrict__ y,
            const float* __restrict__ vals,
            const int* __restrict__ row,
            const int* __restrict__ col) {
    const unsigned FULL = 0xFFFFFFFFu;
    int warpId = (blockIdx.x * blockDim.x + threadIdx.x) >> 5;
    int lane   = threadIdx.x & 31;
    int base   = warpId * 32;

    int   c = col[base + lane];
    int   r = row[base + lane];
    float v = vals[base + lane];

    int half  = lane >> 4;
    int chunk = lane & 15;

    #pragma unroll
    for (int kk = 0; kk < 4; kk++) {
        int cc[4], rr[4];
        float vv[4];
        #pragma unroll
        for (int j = 0; j < 4; j++) {
            int s = (kk * 4 + j) * 2 + half;
            cc[j] = __shfl_sync(FULL, c, s);
            rr[j] = __shfl_sync(FULL, r, s);
            vv[j] = __shfl_sync(FULL, v, s);
        }
        float4 xv[4];
        #pragma unroll
        for (int j = 0; j < 4; j++) {
            if (FIRST) {
                const float4* xp = (cc[j] < NUM_USERS)
                    ? (const float4*)user_emb + (size_t)cc[j] * 16
                    : (const float4*)item_emb + (size_t)(cc[j] - NUM_USERS) * 16;
                xv[j] = xp[chunk];
            } else {
                xv[j] = ((const float4*)x)[(size_t)cc[j] * 16 + chunk];
            }
        }
        #pragma unroll
        for (int j = 0; j < 4; j++) {
            float a = xv[j].x * vv[j];
            float b = xv[j].y * vv[j];
            float cgm = xv[j].z * vv[j];
            float d = xv[j].w * vv[j];
            float* p = y + (size_t)rr[j] * EMB_DIM + chunk * 4;
            asm volatile("red.global.add.v4.f32 [%0], {%1,%2,%3,%4};"
                         :: "l"(p), "f"(a), "f"(b), "f"(cgm), "f"(d)
                         : "memory");
        }
    }
}

// ---------------------------------------------------------------------------
// Masked SpMM (final layer): only edges whose destination row is flagged
// contribute to consumed output. ~8% of edges survive; warp compacts the
// live set via ballot and processes live edges two at a time (half-warp each).
// ---------------------------------------------------------------------------
__global__ void __launch_bounds__(256)
spmm_masked_kernel(const float* __restrict__ x,
                   float* __restrict__ y,
                   const float* __restrict__ vals,
                   const int* __restrict__ row,
                   const int* __restrict__ col) {
    const unsigned FULL = 0xFFFFFFFFu;
    int warpId = (blockIdx.x * blockDim.x + threadIdx.x) >> 5;
    int lane   = threadIdx.x & 31;
    int base   = warpId * 32;

    int   c = col[base + lane];
    int   r = row[base + lane];
    float v = vals[base + lane];

    bool need = (g_flag[r] != 0);
    unsigned m = __ballot_sync(FULL, need);

    int half  = lane >> 4;
    int chunk = lane & 15;

    while (m) {
        int s0 = __ffs(m) - 1; m &= m - 1;
        int s1 = -1;
        if (m) { s1 = __ffs(m) - 1; m &= m - 1; }
        int s = (half == 0) ? s0 : s1;
        bool active = (s >= 0);
        int ssafe = active ? s : 0;
        int   rr = __shfl_sync(FULL, r, ssafe);
        int   cc = __shfl_sync(FULL, c, ssafe);
        float vv = __shfl_sync(FULL, v, ssafe);
        if (active) {
            float4 xv = ((const float4*)x)[(size_t)cc * 16 + chunk];
            float a = xv.x * vv, b = xv.y * vv, cgm = xv.z * vv, d = xv.w * vv;
            float* p = y + (size_t)rr * EMB_DIM + chunk * 4;
            asm volatile("red.global.add.v4.f32 [%0], {%1,%2,%3,%4};"
                         :: "l"(p), "f"(a), "f"(b), "f"(cgm), "f"(d)
                         : "memory");
        }
    }
}

// ---------------------------------------------------------------------------
// Scoring: one warp per batch element.
// acc = x0 + x1 + x2 + x3 (x0 from input tables); score = dot(acc_u,acc_i)/16
// out layout: [pos_scores(4096) | neg_scores(4096)]
// ---------------------------------------------------------------------------
__global__ void score_kernel(const float* __restrict__ user_emb,
                             const float* __restrict__ item_emb,
                             const int* __restrict__ users,
                             const int* __restrict__ pos_items,
                             const int* __restrict__ neg_items,
                             float* __restrict__ out) {
    int warp = (blockIdx.x * blockDim.x + threadIdx.x) >> 5;
    int lane = threadIdx.x & 31;
    if (warp >= BATCH) return;

    int u  = users[warp];
    int pi = pos_items[warp];
    int ni = neg_items[warp];

    const float2* UE = (const float2*)user_emb;
    const float2* IE = (const float2*)item_emb;
    const float2* X1 = (const float2*)g_x1;
    const float2* X2 = (const float2*)g_x2;
    const float2* X3 = (const float2*)g_x3;

    size_t un = (size_t)u * 32 + lane;
    size_t pn = (size_t)(NUM_USERS + pi) * 32 + lane;
    size_t nn = (size_t)(NUM_USERS + ni) * 32 + lane;
    size_t pl = (size_t)pi * 32 + lane;
    size_t nl = (size_t)ni * 32 + lane;

    float2 a, t;
    a = UE[un];
    t = X1[un]; a.x += t.x; a.y += t.y;
    t = X2[un]; a.x += t.x; a.y += t.y;
    t = X3[un]; a.x += t.x; a.y += t.y;
    float2 uacc = a;
    a = IE[pl];
    t = X1[pn]; a.x += t.x; a.y += t.y;
    t = X2[pn]; a.x += t.x; a.y += t.y;
    t = X3[pn]; a.x += t.x; a.y += t.y;
    float2 pacc = a;
    a = IE[nl];
    t = X1[nn]; a.x += t.x; a.y += t.y;
    t = X2[nn]; a.x += t.x; a.y += t.y;
    t = X3[nn]; a.x += t.x; a.y += t.y;
    float2 nacc = a;

    float ps = uacc.x * pacc.x + uacc.y * pacc.y;
    float ns = uacc.x * nacc.x + uacc.y * nacc.y;
    #pragma unroll
    for (int o = 16; o > 0; o >>= 1) {
        ps += __shfl_down_sync(0xFFFFFFFFu, ps, o);
        ns += __shfl_down_sync(0xFFFFFFFFu, ns, o);
    }
    if (lane == 0) {
        out[warp]         = ps * (1.0f / 16.0f);
        out[BATCH + warp] = ns * (1.0f / 16.0f);
    }
}

// ---------------------------------------------------------------------------
extern "C" void kernel_launch(void* const* d_in, const int* in_sizes, int n_in,
                              void* d_out, int out_size) {
    const float* user_emb  = (const float*)d_in[0];
    const float* item_emb  = (const float*)d_in[1];
    const float* vals      = (const float*)d_in[2];
    const int*   row       = (const int*)d_in[3];
    const int*   col       = (const int*)d_in[4];
    const int*   users     = (const int*)d_in[5];
    const int*   pos_items = (const int*)d_in[6];
    const int*   neg_items = (const int*)d_in[7];
    float* out = (float*)d_out;

    float* x1P; cudaGetSymbolAddress((void**)&x1P, g_x1);
    float* x2P; cudaGetSymbolAddress((void**)&x2P, g_x2);
    float* x3P; cudaGetSymbolAddress((void**)&x3P, g_x3);

    const int TB = 256;
    const int zeroBlocks = (NV4 + TB - 1) / TB;
    const int spmmBlocks = (N_EDGES / 32) * 32 / TB;   // 15625 blocks

    zero_kernel<<<zeroBlocks, TB>>>();
    mark_kernel<<<(BATCH + TB - 1) / TB, TB>>>(users, pos_items, neg_items);

    // Layer 1: x0 (inputs) -> x1
    spmm_kernel<true><<<spmmBlocks, TB>>>(nullptr, user_emb, item_emb, x1P,
                                          vals, row, col);
    // Layer 2: x1 -> x2
    spmm_kernel<false><<<spmmBlocks, TB>>>(x1P, nullptr, nullptr, x2P,
                                           vals, row, col);
    // Layer 3 (masked): x2 -> x3, only rows consumed by scoring
    spmm_masked_kernel<<<spmmBlocks, TB>>>(x2P, x3P, vals, row, col);

    score_kernel<<<(BATCH * 32) / TB, TB>>>(user_emb, item_emb,
                                            users, pos_items, neg_items, out);
}

// round 4
// speedup vs baseline: 1.9042x; 1.0048x over previous
#include <cuda_runtime.h>
#include <cuda_bf16.h>
#include <cstdint>

#define NUM_USERS 100000
#define NUM_ITEMS 50000
#define EMB_DIM   64
#define N_NODES   (NUM_USERS + NUM_ITEMS)   // 150000
#define N_EDGES   4000000
#define BATCH     4096
#define NFLOAT    (N_NODES * EMB_DIM)        // 9,600,000
#define NV4       (NFLOAT / 4)               // 2,400,000

// Layer outputs + needed-node flags (device-global scratch)
__device__ float g_x1[NFLOAT];
__device__ float g_x2[NFLOAT];
__device__ float g_x3[NFLOAT];
__device__ int   g_flag[N_NODES];

// ---------------------------------------------------------------------------
// Zero the three layer-output buffers + flags.
// ---------------------------------------------------------------------------
__global__ void zero_kernel() {
    int i = blockIdx.x * blockDim.x + threadIdx.x;
    if (i < NV4) {
        float4 z = make_float4(0.f, 0.f, 0.f, 0.f);
        ((float4*)g_x1)[i] = z;
        ((float4*)g_x2)[i] = z;
        ((float4*)g_x3)[i] = z;
    }
    if (i < N_NODES) g_flag[i] = 0;
}

// ---------------------------------------------------------------------------
// Mark nodes whose final (layer-3) output is actually consumed by scoring.
// ---------------------------------------------------------------------------
__global__ void mark_kernel(const int* __restrict__ users,
                            const int* __restrict__ pos_items,
                            const int* __restrict__ neg_items) {
    int i = blockIdx.x * blockDim.x + threadIdx.x;
    if (i >= BATCH) return;
    g_flag[users[i]]                 = 1;
    g_flag[NUM_USERS + pos_items[i]] = 1;
    g_flag[NUM_USERS + neg_items[i]] = 1;
}

// ---------------------------------------------------------------------------
// Full SpMM: y[row[e]] += vals[e] * x[col[e]]   (y pre-zeroed)
// One warp owns 32 edges: metadata loaded coalesced, shfl-broadcast.
// Each edge handled by 16 lanes (one float4 each); 4 edge-pairs in flight.
// FIRST=true reads x0 from the two input embedding tables (concat semantics).
// ---------------------------------------------------------------------------
template<bool FIRST>
__global__ void __launch_bounds__(256)
spmm_kernel(const float* __restrict__ x,
            const float* __restrict__ user_emb,
            const float* __restrict__ item_emb,
            float* __restrict__ y,
            const float* __restrict__ vals,
            const int* __restrict__ row,
            const int* __restrict__ col) {
    const unsigned FULL = 0xFFFFFFFFu;
    int warpId = (blockIdx.x * blockDim.x + threadIdx.x) >> 5;
    int lane   = threadIdx.x & 31;
    int base   = warpId * 32;

    int   c = col[base + lane];
    int   r = row[base + lane];
    float v = vals[base + lane];

    int half  = lane >> 4;
    int chunk = lane & 15;

    #pragma unroll
    for (int kk = 0; kk < 4; kk++) {
        int cc[4], rr[4];
        float vv[4];
        #pragma unroll
        for (int j = 0; j < 4; j++) {
            int s = (kk * 4 + j) * 2 + half;
            cc[j] = __shfl_sync(FULL, c, s);
            rr[j] = __shfl_sync(FULL, r, s);
            vv[j] = __shfl_sync(FULL, v, s);
        }
        float4 xv[4];
        #pragma unroll
        for (int j = 0; j < 4; j++) {
            if (FIRST) {
                const float4* xp = (cc[j] < NUM_USERS)
                    ? (const float4*)user_emb + (size_t)cc[j] * 16
                    : (const float4*)item_emb + (size_t)(cc[j] - NUM_USERS) * 16;
                xv[j] = xp[chunk];
            } else {
                xv[j] = ((const float4*)x)[(size_t)cc[j] * 16 + chunk];
            }
        }
        #pragma unroll
        for (int j = 0; j < 4; j++) {
            float a = xv[j].x * vv[j];
            float b = xv[j].y * vv[j];
            float cgm = xv[j].z * vv[j];
            float d = xv[j].w * vv[j];
            float* p = y + (size_t)rr[j] * EMB_DIM + chunk * 4;
            asm volatile("red.global.add.v4.f32 [%0], {%1,%2,%3,%4};"
                         :: "l"(p), "f"(a), "f"(b), "f"(cgm), "f"(d)
                         : "memory");
        }
    }
}

// ---------------------------------------------------------------------------
// Masked SpMM (final layer): only edges whose destination row is flagged
// contribute to consumed output. ~8% of edges survive; warp compacts the
// live set via ballot and processes live edges two at a time (half-warp each).
// ---------------------------------------------------------------------------
__global__ void __launch_bounds__(256)
spmm_masked_kernel(const float* __restrict__ x,
                   float* __restrict__ y,
                   const float* __restrict__ vals,
                   const int* __restrict__ row,
                   const int* __restrict__ col) {
    const unsigned FULL = 0xFFFFFFFFu;
    int warpId = (blockIdx.x * blockDim.x + threadIdx.x) >> 5;
    int lane   = threadIdx.x & 31;
    int base   = warpId * 32;

    int   c = col[base + lane];
    int   r = row[base + lane];
    float v = vals[base + lane];

    bool need = (g_flag[r] != 0);
    unsigned m = __ballot_sync(FULL, need);

    int half  = lane >> 4;
    int chunk = lane & 15;

    while (m) {
        int s0 = __ffs(m) - 1; m &= m - 1;
        int s1 = -1;
        if (m) { s1 = __ffs(m) - 1; m &= m - 1; }
        int s = (half == 0) ? s0 : s1;
        bool active = (s >= 0);
        int ssafe = active ? s : 0;
        int   rr = __shfl_sync(FULL, r, ssafe);
        int   cc = __shfl_sync(FULL, c, ssafe);
        float vv = __shfl_sync(FULL, v, ssafe);
        if (active) {
            float4 xv = ((const float4*)x)[(size_t)cc * 16 + chunk];
            float a = xv.x * vv, b = xv.y * vv, cgm = xv.z * vv, d = xv.w * vv;
            float* p = y + (size_t)rr * EMB_DIM + chunk * 4;
            asm volatile("red.global.add.v4.f32 [%0], {%1,%2,%3,%4};"
                         :: "l"(p), "f"(a), "f"(b), "f"(cgm), "f"(d)
                         : "memory");
        }
    }
}

// ---------------------------------------------------------------------------
// Scoring: one warp per batch element.
// acc = x0 + x1 + x2 + x3 (x0 from input tables); score = dot(acc_u,acc_i)/16
// out layout: [pos_scores(4096) | neg_scores(4096)]
// ---------------------------------------------------------------------------
__global__ void score_kernel(const float* __restrict__ user_emb,
                             const float* __restrict__ item_emb,
                             const int* __restrict__ users,
                             const int* __restrict__ pos_items,
                             const int* __restrict__ neg_items,
                             float* __restrict__ out) {
    int warp = (blockIdx.x * blockDim.x + threadIdx.x) >> 5;
    int lane = threadIdx.x & 31;
    if (warp >= BATCH) return;

    int u  = users[warp];
    int pi = pos_items[warp];
    int ni = neg_items[warp];

    const float2* UE = (const float2*)user_emb;
    const float2* IE = (const float2*)item_emb;
    const float2* X1 = (const float2*)g_x1;
    const float2* X2 = (const float2*)g_x2;
    const float2* X3 = (const float2*)g_x3;

    size_t un = (size_t)u * 32 + lane;
    size_t pn = (size_t)(NUM_USERS + pi) * 32 + lane;
    size_t nn = (size_t)(NUM_USERS + ni) * 32 + lane;
    size_t pl = (size_t)pi * 32 + lane;
    size_t nl = (size_t)ni * 32 + lane;

    float2 a, t;
    a = UE[un];
    t = X1[un]; a.x += t.x; a.y += t.y;
    t = X2[un]; a.x += t.x; a.y += t.y;
    t = X3[un]; a.x += t.x; a.y += t.y;
    float2 uacc = a;
    a = IE[pl];
    t = X1[pn]; a.x += t.x; a.y += t.y;
    t = X2[pn]; a.x += t.x; a.y += t.y;
    t = X3[pn]; a.x += t.x; a.y += t.y;
    float2 pacc = a;
    a = IE[nl];
    t = X1[nn]; a.x += t.x; a.y += t.y;
    t = X2[nn]; a.x += t.x; a.y += t.y;
    t = X3[nn]; a.x += t.x; a.y += t.y;
    float2 nacc = a;

    float ps = uacc.x * pacc.x + uacc.y * pacc.y;
    float ns = uacc.x * nacc.x + uacc.y * nacc.y;
    #pragma unroll
    for (int o = 16; o > 0; o >>= 1) {
        ps += __shfl_down_sync(0xFFFFFFFFu, ps, o);
        ns += __shfl_down_sync(0xFFFFFFFFu, ns, o);
    }
    if (lane == 0) {
        out[warp]         = ps * (1.0f / 16.0f);
        out[BATCH + warp] = ns * (1.0f / 16.0f);
    }
}

// ---------------------------------------------------------------------------
extern "C" void kernel_launch(void* const* d_in, const int* in_sizes, int n_in,
                              void* d_out, int out_size) {
    const float* user_emb  = (const float*)d_in[0];
    const float* item_emb  = (const float*)d_in[1];
    const float* vals      = (const float*)d_in[2];
    const int*   row       = (const int*)d_in[3];
    const int*   col       = (const int*)d_in[4];
    const int*   users     = (const int*)d_in[5];
    const int*   pos_items = (const int*)d_in[6];
    const int*   neg_items = (const int*)d_in[7];
    float* out = (float*)d_out;

    float* x1P; cudaGetSymbolAddress((void**)&x1P, g_x1);
    float* x2P; cudaGetSymbolAddress((void**)&x2P, g_x2);
    float* x3P; cudaGetSymbolAddress((void**)&x3P, g_x3);

    const int TB = 256;
    const int zeroBlocks = (NV4 + TB - 1) / TB;
    const int spmmBlocks = (N_EDGES / 32) * 32 / TB;   // 15625 blocks

    zero_kernel<<<zeroBlocks, TB>>>();
    mark_kernel<<<(BATCH + TB - 1) / TB, TB>>>(users, pos_items, neg_items);

    // Layer 1: x0 (inputs) -> x1
    spmm_kernel<true><<<spmmBlocks, TB>>>(nullptr, user_emb, item_emb, x1P,
                                          vals, row, col);
    // Layer 2: x1 -> x2
    spmm_kernel<false><<<spmmBlocks, TB>>>(x1P, nullptr, nullptr, x2P,
                                           vals, row, col);
    // Layer 3 (masked): x2 -> x3, only rows consumed by scoring
    spmm_masked_kernel<<<spmmBlocks, TB>>>(x2P, x3P, vals, row, col);

    score_kernel<<<(BATCH * 32) / TB, TB>>>(user_emb, item_emb,
                                            users, pos_items, neg_items, out);
}

// round 5
// speedup vs baseline: 2.6055x; 1.3683x over previous
#include <cuda_runtime.h>
#include <cuda_bf16.h>
#include <cstdint>

#define NUM_USERS 100000
#define NUM_ITEMS 50000
#define EMB_DIM   64
#define N_NODES   (NUM_USERS + NUM_ITEMS)   // 150000
#define N_EDGES   4000000
#define BATCH     4096
#define NFLOAT    (N_NODES * EMB_DIM)        // 9,600,000

#define SCAN_BLK  1024
#define SCAN_NB   ((N_NODES + SCAN_BLK - 1) / SCAN_BLK)   // 147

// Device-global scratch (no runtime allocation allowed)
__device__ float g_x1[NFLOAT];
__device__ float g_x2[NFLOAT];
__device__ float g_x3[NFLOAT];
__device__ int   g_flag[N_NODES];
__device__ int   g_deg[N_NODES];
__device__ int   g_start[N_NODES];
__device__ int   g_fill[N_NODES];
__device__ int   g_bsum[256];
__device__ int   g_boff[256];
__device__ int2  g_epack[N_EDGES];           // (col, val-bits) grouped by row

// ---------------------------------------------------------------------------
// Clear per-call counters/flags (layer buffers need no zeroing: pull-mode
// spmm writes every produced row exactly once).
// ---------------------------------------------------------------------------
__global__ void zero_small_kernel() {
    int i = blockIdx.x * blockDim.x + threadIdx.x;
    if (i < N_NODES) { g_deg[i] = 0; g_flag[i] = 0; }
}

__global__ void mark_kernel(const int* __restrict__ users,
                            const int* __restrict__ pos_items,
                            const int* __restrict__ neg_items) {
    int i = blockIdx.x * blockDim.x + threadIdx.x;
    if (i >= BATCH) return;
    g_flag[users[i]]                 = 1;
    g_flag[NUM_USERS + pos_items[i]] = 1;
    g_flag[NUM_USERS + neg_items[i]] = 1;
}

// ---------------------------------------------------------------------------
// CSR build: histogram -> block scan (3 kernels) -> packed scatter
// ---------------------------------------------------------------------------
__global__ void hist_kernel(const int* __restrict__ row) {
    int i = blockIdx.x * blockDim.x + threadIdx.x;
    if (i < N_EDGES) atomicAdd(&g_deg[row[i]], 1);
}

__global__ void scan1_kernel() {                     // per-block exclusive scan
    __shared__ int sm[SCAN_BLK];
    int tid = threadIdx.x;
    int i = blockIdx.x * SCAN_BLK + tid;
    int d = (i < N_NODES) ? g_deg[i] : 0;
    sm[tid] = d;
    __syncthreads();
    #pragma unroll
    for (int off = 1; off < SCAN_BLK; off <<= 1) {
        int t = (tid >= off) ? sm[tid - off] : 0;
        __syncthreads();
        sm[tid] += t;
        __syncthreads();
    }
    if (i < N_NODES) g_start[i] = sm[tid] - d;       // exclusive
    if (tid == SCAN_BLK - 1) g_bsum[blockIdx.x] = sm[tid];
}

__global__ void scan2_kernel() {                     // scan the 147 block sums
    __shared__ int sm[256];
    int tid = threadIdx.x;
    int d = (tid < SCAN_NB) ? g_bsum[tid] : 0;
    sm[tid] = d;
    __syncthreads();
    #pragma unroll
    for (int off = 1; off < 256; off <<= 1) {
        int t = (tid >= off) ? sm[tid - off] : 0;
        __syncthreads();
        sm[tid] += t;
        __syncthreads();
    }
    if (tid < SCAN_NB) g_boff[tid] = sm[tid] - d;    // exclusive
}

__global__ void scan3_kernel() {                     // add block offsets
    int i = blockIdx.x * SCAN_BLK + threadIdx.x;
    if (i < N_NODES) {
        int s = g_start[i] + g_boff[blockIdx.x];
        g_start[i] = s;
        g_fill[i]  = s;
    }
}

__global__ void scatter_kernel(const int* __restrict__ row,
                               const int* __restrict__ col,
                               const float* __restrict__ vals) {
    int i = blockIdx.x * blockDim.x + threadIdx.x;
    if (i >= N_EDGES) return;
    int p = atomicAdd(&g_fill[row[i]], 1);
    g_epack[p] = make_int2(col[i], __float_as_int(vals[i]));
}

// ---------------------------------------------------------------------------
// Pull-mode CSR SpMM: one warp per row.
//   y[r] = sum_{k in row r} val_k * x[col_k]
// Each lane owns 2 floats of the 64-dim embedding (float2, coalesced 256B).
// Neighbor (col,val) loaded coalesced in groups of 32, shfl-broadcast.
// FIRST: x is concat(user_emb, item_emb). MASKED: skip unflagged rows.
// ---------------------------------------------------------------------------
template<bool FIRST, bool MASKED>
__global__ void __launch_bounds__(256)
spmm_csr_kernel(const float* __restrict__ x,
                const float* __restrict__ user_emb,
                const float* __restrict__ item_emb,
                float* __restrict__ y) {
    const unsigned FULL = 0xFFFFFFFFu;
    int r    = (blockIdx.x * blockDim.x + threadIdx.x) >> 5;
    int lane = threadIdx.x & 31;
    if (r >= N_NODES) return;
    if (MASKED && g_flag[r] == 0) return;

    int start = g_start[r];
    int deg   = g_deg[r];

    float ax = 0.f, ay = 0.f;

    int k = 0;
    for (; k + 32 <= deg; k += 32) {
        int2 pk = g_epack[start + k + lane];
        #pragma unroll 8
        for (int j = 0; j < 32; j++) {
            int   cc = __shfl_sync(FULL, pk.x, j);
            float vv = __int_as_float(__shfl_sync(FULL, pk.y, j));
            float2 xv;
            if (FIRST) {
                const float2* xp = (cc < NUM_USERS)
                    ? (const float2*)user_emb + (size_t)cc * 32
                    : (const float2*)item_emb + (size_t)(cc - NUM_USERS) * 32;
                xv = xp[lane];
            } else {
                xv = ((const float2*)x)[(size_t)cc * 32 + lane];
            }
            ax += vv * xv.x;
            ay += vv * xv.y;
        }
    }
    int n = deg - k;
    if (n > 0) {
        int2 pk = (lane < n) ? g_epack[start + k + lane] : make_int2(0, 0);
        for (int j = 0; j < n; j++) {
            int   cc = __shfl_sync(FULL, pk.x, j);
            float vv = __int_as_float(__shfl_sync(FULL, pk.y, j));
            float2 xv;
            if (FIRST) {
                const float2* xp = (cc < NUM_USERS)
                    ? (const float2*)user_emb + (size_t)cc * 32
                    : (const float2*)item_emb + (size_t)(cc - NUM_USERS) * 32;
                xv = xp[lane];
            } else {
                xv = ((const float2*)x)[(size_t)cc * 32 + lane];
            }
            ax += vv * xv.x;
            ay += vv * xv.y;
        }
    }

    ((float2*)y)[(size_t)r * 32 + lane] = make_float2(ax, ay);
}

// ---------------------------------------------------------------------------
// Scoring: one warp per batch element.
// acc = x0 + x1 + x2 + x3 (x0 from input tables); score = dot(acc_u,acc_i)/16
// out layout: [pos_scores(4096) | neg_scores(4096)]
// ---------------------------------------------------------------------------
__global__ void score_kernel(const float* __restrict__ user_emb,
                             const float* __restrict__ item_emb,
                             const int* __restrict__ users,
                             const int* __restrict__ pos_items,
                             const int* __restrict__ neg_items,
                             float* __restrict__ out) {
    int warp = (blockIdx.x * blockDim.x + threadIdx.x) >> 5;
    int lane = threadIdx.x & 31;
    if (warp >= BATCH) return;

    int u  = users[warp];
    int pi = pos_items[warp];
    int ni = neg_items[warp];

    const float2* UE = (const float2*)user_emb;
    const float2* IE = (const float2*)item_emb;
    const float2* X1 = (const float2*)g_x1;
    const float2* X2 = (const float2*)g_x2;
    const float2* X3 = (const float2*)g_x3;

    size_t un = (size_t)u * 32 + lane;
    size_t pn = (size_t)(NUM_USERS + pi) * 32 + lane;
    size_t nn = (size_t)(NUM_USERS + ni) * 32 + lane;
    size_t pl = (size_t)pi * 32 + lane;
    size_t nl = (size_t)ni * 32 + lane;

    float2 a, t;
    a = UE[un];
    t = X1[un]; a.x += t.x; a.y += t.y;
    t = X2[un]; a.x += t.x; a.y += t.y;
    t = X3[un]; a.x += t.x; a.y += t.y;
    float2 uacc = a;
    a = IE[pl];
    t = X1[pn]; a.x += t.x; a.y += t.y;
    t = X2[pn]; a.x += t.x; a.y += t.y;
    t = X3[pn]; a.x += t.x; a.y += t.y;
    float2 pacc = a;
    a = IE[nl];
    t = X1[nn]; a.x += t.x; a.y += t.y;
    t = X2[nn]; a.x += t.x; a.y += t.y;
    t = X3[nn]; a.x += t.x; a.y += t.y;
    float2 nacc = a;

    float ps = uacc.x * pacc.x + uacc.y * pacc.y;
    float ns = uacc.x * nacc.x + uacc.y * nacc.y;
    #pragma unroll
    for (int o = 16; o > 0; o >>= 1) {
        ps += __shfl_down_sync(0xFFFFFFFFu, ps, o);
        ns += __shfl_down_sync(0xFFFFFFFFu, ns, o);
    }
    if (lane == 0) {
        out[warp]         = ps * (1.0f / 16.0f);
        out[BATCH + warp] = ns * (1.0f / 16.0f);
    }
}

// ---------------------------------------------------------------------------
extern "C" void kernel_launch(void* const* d_in, const int* in_sizes, int n_in,
                              void* d_out, int out_size) {
    const float* user_emb  = (const float*)d_in[0];
    const float* item_emb  = (const float*)d_in[1];
    const float* vals      = (const float*)d_in[2];
    const int*   row       = (const int*)d_in[3];
    const int*   col       = (const int*)d_in[4];
    const int*   users     = (const int*)d_in[5];
    const int*   pos_items = (const int*)d_in[6];
    const int*   neg_items = (const int*)d_in[7];
    float* out = (float*)d_out;

    float* x1P; cudaGetSymbolAddress((void**)&x1P, g_x1);
    float* x2P; cudaGetSymbolAddress((void**)&x2P, g_x2);
    float* x3P; cudaGetSymbolAddress((void**)&x3P, g_x3);

    const int TB = 256;
    const int edgeBlocks = (N_EDGES + TB - 1) / TB;
    const int rowWarpBlocks = (N_NODES * 32 + TB - 1) / TB;   // warp per row

    // Per-call counters / flags
    zero_small_kernel<<<(N_NODES + SCAN_BLK - 1) / SCAN_BLK, SCAN_BLK>>>();
    mark_kernel<<<(BATCH + TB - 1) / TB, TB>>>(users, pos_items, neg_items);

    // CSR build
    hist_kernel<<<edgeBlocks, TB>>>(row);
    scan1_kernel<<<SCAN_NB, SCAN_BLK>>>();
    scan2_kernel<<<1, 256>>>();
    scan3_kernel<<<SCAN_NB, SCAN_BLK>>>();
    scatter_kernel<<<edgeBlocks, TB>>>(row, col, vals);

    // Layer 1: x0 (input tables) -> x1
    spmm_csr_kernel<true, false><<<rowWarpBlocks, TB>>>(nullptr, user_emb,
                                                        item_emb, x1P);
    // Layer 2: x1 -> x2
    spmm_csr_kernel<false, false><<<rowWarpBlocks, TB>>>(x1P, nullptr,
                                                         nullptr, x2P);
    // Layer 3 (masked): x2 -> x3, only rows consumed by scoring
    spmm_csr_kernel<false, true><<<rowWarpBlocks, TB>>>(x2P, nullptr,
                                                        nullptr, x3P);

    score_kernel<<<(BATCH * 32) / TB, TB>>>(user_emb, item_emb,
                                            users, pos_items, neg_items, out);
}

// round 8
// speedup vs baseline: 2.7896x; 1.0707x over previous
#include <cuda_runtime.h>
#include <cuda_fp16.h>
#include <cstdint>

#define NUM_USERS 100000
#define NUM_ITEMS 50000
#define EMB_DIM   64
#define N_NODES   (NUM_USERS + NUM_ITEMS)   // 150000
#define N_EDGES   4000000
#define BATCH     4096
#define NFLOAT    (N_NODES * EMB_DIM)        // 9,600,000
#define NV4       (NFLOAT / 4)               // 2,400,000

#define SCAN_BLK  1024
#define SCAN_NB   ((N_NODES + SCAN_BLK - 1) / SCAN_BLK)   // 147

// Device-global scratch (no runtime allocation allowed)
__device__ float  g_x1[NFLOAT];              // fp32 layer outputs (score path)
__device__ float  g_x2[NFLOAT];
__device__ float  g_x3[NFLOAT];
__device__ __half g_h0[NFLOAT];              // fp16 gather operand, layer 1
__device__ __half g_h1[NFLOAT];              // fp16 gather operand, layer 2
__device__ int    g_deg[N_NODES];
__device__ int    g_start[N_NODES];
__device__ int    g_fill[N_NODES];
__device__ int    g_bsum[256];
__device__ int    g_boff[256];
__device__ int    g_list[3 * BATCH];         // rows needed from layer 3
__device__ int2   g_epack[N_EDGES];          // (col, val-bits) grouped by row

// ---------------------------------------------------------------------------
// Prep: zero degree counters + build the layer-3 row list (fixed slots, dups ok)
// ---------------------------------------------------------------------------
__global__ void prep_kernel(const int* __restrict__ users,
                            const int* __restrict__ pos_items,
                            const int* __restrict__ neg_items) {
    int i = blockIdx.x * blockDim.x + threadIdx.x;
    if (i < N_NODES) g_deg[i] = 0;
    if (i < BATCH) {
        g_list[i]             = users[i];
        g_list[BATCH + i]     = NUM_USERS + pos_items[i];
        g_list[2 * BATCH + i] = NUM_USERS + neg_items[i];
    }
}

// ---------------------------------------------------------------------------
// x0 -> fp16 shadow (concat semantics)
// ---------------------------------------------------------------------------
__global__ void tohalf_kernel(const float* __restrict__ user_emb,
                              const float* __restrict__ item_emb) {
    int i = blockIdx.x * blockDim.x + threadIdx.x;   // float4 index
    if (i >= NV4) return;
    int node = i >> 4;
    float4 v = (node < NUM_USERS)
        ? ((const float4*)user_emb)[i]
        : ((const float4*)item_emb)[i - NUM_USERS * (EMB_DIM / 4)];
    __half2 h0 = __floats2half2_rn(v.x, v.y);
    __half2 h1 = __floats2half2_rn(v.z, v.w);
    ((__half2*)g_h0)[2 * i]     = h0;
    ((__half2*)g_h0)[2 * i + 1] = h1;
}

// ---------------------------------------------------------------------------
// CSR build: histogram -> block scan (3 kernels) -> packed scatter
// ---------------------------------------------------------------------------
__global__ void hist_kernel(const int* __restrict__ row) {
    int i = blockIdx.x * blockDim.x + threadIdx.x;
    if (i < N_EDGES) atomicAdd(&g_deg[row[i]], 1);
}

__global__ void scan1_kernel() {                     // per-block exclusive scan
    __shared__ int sm[SCAN_BLK];
    int tid = threadIdx.x;
    int i = blockIdx.x * SCAN_BLK + tid;
    int d = (i < N_NODES) ? g_deg[i] : 0;
    sm[tid] = d;
    __syncthreads();
    #pragma unroll
    for (int off = 1; off < SCAN_BLK; off <<= 1) {
        int t = (tid >= off) ? sm[tid - off] : 0;
        __syncthreads();
        sm[tid] += t;
        __syncthreads();
    }
    if (i < N_NODES) g_start[i] = sm[tid] - d;       // exclusive
    if (tid == SCAN_BLK - 1) g_bsum[blockIdx.x] = sm[tid];
}

__global__ void scan2_kernel() {                     // scan the 147 block sums
    __shared__ int sm[256];
    int tid = threadIdx.x;
    int d = (tid < SCAN_NB) ? g_bsum[tid] : 0;
    sm[tid] = d;
    __syncthreads();
    #pragma unroll
    for (int off = 1; off < 256; off <<= 1) {
        int t = (tid >= off) ? sm[tid - off] : 0;
        __syncthreads();
        sm[tid] += t;
        __syncthreads();
    }
    if (tid < SCAN_NB) g_boff[tid] = sm[tid] - d;    // exclusive
}

__global__ void scan3_kernel() {                     // add block offsets
    int i = blockIdx.x * SCAN_BLK + threadIdx.x;
    if (i < N_NODES) {
        int s = g_start[i] + g_boff[blockIdx.x];
        g_start[i] = s;
        g_fill[i]  = s;
    }
}

__global__ void scatter_kernel(const int* __restrict__ row,
                               const int* __restrict__ col,
                               const float* __restrict__ vals) {
    int i = blockIdx.x * blockDim.x + threadIdx.x;
    if (i >= N_EDGES) return;
    int p = atomicAdd(&g_fill[row[i]], 1);
    g_epack[p] = make_int2(col[i], __float_as_int(vals[i]));
}

// ---------------------------------------------------------------------------
// Pull-mode CSR SpMM, fp16 gather operand, fp32 accumulate.
//   y[r] = sum_{k in row r} val_k * xh[col_k]
// One warp per row; lane owns 2 dims (half2 load = 128 B/row coalesced).
// WRITE_HALF: also emit fp16 shadow for the next layer.
// ---------------------------------------------------------------------------
template<bool WRITE_HALF>
__global__ void __launch_bounds__(256)
spmm_csr_kernel(const __half2* __restrict__ xh,
                float* __restrict__ y,
                __half* __restrict__ yh) {
    const unsigned FULL = 0xFFFFFFFFu;
    int r    = (blockIdx.x * blockDim.x + threadIdx.x) >> 5;
    int lane = threadIdx.x & 31;
    if (r >= N_NODES) return;

    int start = g_start[r];
    int deg   = g_deg[r];

    float ax = 0.f, ay = 0.f;

    int k = 0;
    for (; k + 32 <= deg; k += 32) {
        int2 pk = g_epack[start + k + lane];
        #pragma unroll 8
        for (int j = 0; j < 32; j++) {
            int   cc = __shfl_sync(FULL, pk.x, j);
            float vv = __int_as_float(__shfl_sync(FULL, pk.y, j));
            float2 xv = __half22float2(xh[(size_t)cc * 32 + lane]);
            ax += vv * xv.x;
            ay += vv * xv.y;
        }
    }
    int n = deg - k;
    if (n > 0) {
        int2 pk = (lane < n) ? g_epack[start + k + lane] : make_int2(0, 0);
        for (int j = 0; j < n; j++) {
            int   cc = __shfl_sync(FULL, pk.x, j);
            float vv = __int_as_float(__shfl_sync(FULL, pk.y, j));
            float2 xv = __half22float2(xh[(size_t)cc * 32 + lane]);
            ax += vv * xv.x;
            ay += vv * xv.y;
        }
    }

    ((float2*)y)[(size_t)r * 32 + lane] = make_float2(ax, ay);
    if (WRITE_HALF) {
        ((__half2*)yh)[(size_t)r * 32 + lane] = __floats2half2_rn(ax, ay);
    }
}

// ---------------------------------------------------------------------------
// Masked layer-3 SpMM: rows from g_list (only scored rows, ~12K warps),
// gathers fp32 x2 directly (no fp16 shadow needed for this layer).
// ---------------------------------------------------------------------------
__global__ void __launch_bounds__(256)
spmm_csr_masked_kernel(const float* __restrict__ x,
                       float* __restrict__ y) {
    const unsigned FULL = 0xFFFFFFFFu;
    int w    = (blockIdx.x * blockDim.x + threadIdx.x) >> 5;
    int lane = threadIdx.x & 31;
    if (w >= 3 * BATCH) return;
    int r = g_list[w];

    int start = g_start[r];
    int deg   = g_deg[r];

    float ax = 0.f, ay = 0.f;

    int k = 0;
    for (; k + 32 <= deg; k += 32) {
        int2 pk = g_epack[start + k + lane];
        #pragma unroll 8
        for (int j = 0; j < 32; j++) {
            int   cc = __shfl_sync(FULL, pk.x, j);
            float vv = __int_as_float(__shfl_sync(FULL, pk.y, j));
            float2 xv = ((const float2*)x)[(size_t)cc * 32 + lane];
            ax += vv * xv.x;
            ay += vv * xv.y;
        }
    }
    int n = deg - k;
    if (n > 0) {
        int2 pk = (lane < n) ? g_epack[start + k + lane] : make_int2(0, 0);
        for (int j = 0; j < n; j++) {
            int   cc = __shfl_sync(FULL, pk.x, j);
            float vv = __int_as_float(__shfl_sync(FULL, pk.y, j));
            float2 xv = ((const float2*)x)[(size_t)cc * 32 + lane];
            ax += vv * xv.x;
            ay += vv * xv.y;
        }
    }

    ((float2*)y)[(size_t)r * 32 + lane] = make_float2(ax, ay);
}

// ---------------------------------------------------------------------------
// Scoring: one warp per batch element.
// acc = x0 + x1 + x2 + x3 (x0 from fp32 input tables); score = dot/16
// out layout: [pos_scores(4096) | neg_scores(4096)]
// ---------------------------------------------------------------------------
__global__ void score_kernel(const float* __restrict__ user_emb,
                             const float* __restrict__ item_emb,
                             const int* __restrict__ users,
                             const int* __restrict__ pos_items,
                             const int* __restrict__ neg_items,
                             float* __restrict__ out) {
    int warp = (blockIdx.x * blockDim.x + threadIdx.x) >> 5;
    int lane = threadIdx.x & 31;
    if (warp >= BATCH) return;

    int u  = users[warp];
    int pi = pos_items[warp];
    int ni = neg_items[warp];

    const float2* UE = (const float2*)user_emb;
    const float2* IE = (const float2*)item_emb;
    const float2* X1 = (const float2*)g_x1;
    const float2* X2 = (const float2*)g_x2;
    const float2* X3 = (const float2*)g_x3;

    size_t un = (size_t)u * 32 + lane;
    size_t pn = (size_t)(NUM_USERS + pi) * 32 + lane;
    size_t nn = (size_t)(NUM_USERS + ni) * 32 + lane;
    size_t pl = (size_t)pi * 32 + lane;
    size_t nl = (size_t)ni * 32 + lane;

    float2 a, t;
    a = UE[un];
    t = X1[un]; a.x += t.x; a.y += t.y;
    t = X2[un]; a.x += t.x; a.y += t.y;
    t = X3[un]; a.x += t.x; a.y += t.y;
    float2 uacc = a;
    a = IE[pl];
    t = X1[pn]; a.x += t.x; a.y += t.y;
    t = X2[pn]; a.x += t.x; a.y += t.y;
    t = X3[pn]; a.x += t.x; a.y += t.y;
    float2 pacc = a;
    a = IE[nl];
    t = X1[nn]; a.x += t.x; a.y += t.y;
    t = X2[nn]; a.x += t.x; a.y += t.y;
    t = X3[nn]; a.x += t.x; a.y += t.y;
    float2 nacc = a;

    float ps = uacc.x * pacc.x + uacc.y * pacc.y;
    float ns = uacc.x * nacc.x + uacc.y * nacc.y;
    #pragma unroll
    for (int o = 16; o > 0; o >>= 1) {
        ps += __shfl_down_sync(0xFFFFFFFFu, ps, o);
        ns += __shfl_down_sync(0xFFFFFFFFu, ns, o);
    }
    if (lane == 0) {
        out[warp]         = ps * (1.0f / 16.0f);
        out[BATCH + warp] = ns * (1.0f / 16.0f);
    }
}

// ---------------------------------------------------------------------------
extern "C" void kernel_launch(void* const* d_in, const int* in_sizes, int n_in,
                              void* d_out, int out_size) {
    const float* user_emb  = (const float*)d_in[0];
    const float* item_emb  = (const float*)d_in[1];
    const float* vals      = (const float*)d_in[2];
    const int*   row       = (const int*)d_in[3];
    const int*   col       = (const int*)d_in[4];
    const int*   users     = (const int*)d_in[5];
    const int*   pos_items = (const int*)d_in[6];
    const int*   neg_items = (const int*)d_in[7];
    float* out = (float*)d_out;

    float*  x1P; cudaGetSymbolAddress((void**)&x1P, g_x1);
    float*  x2P; cudaGetSymbolAddress((void**)&x2P, g_x2);
    float*  x3P; cudaGetSymbolAddress((void**)&x3P, g_x3);
    __half* h0P; cudaGetSymbolAddress((void**)&h0P, g_h0);
    __half* h1P; cudaGetSymbolAddress((void**)&h1P, g_h1);

    const int TB = 256;
    const int edgeBlocks     = (N_EDGES + TB - 1) / TB;
    const int rowWarpBlocks  = (N_NODES * 32 + TB - 1) / TB;    // warp per row
    const int maskWarpBlocks = (3 * BATCH * 32) / TB;           // 1536 blocks

    prep_kernel<<<(N_NODES + TB - 1) / TB, TB>>>(users, pos_items, neg_items);
    tohalf_kernel<<<(NV4 + TB - 1) / TB, TB>>>(user_emb, item_emb);

    // CSR build
    hist_kernel<<<edgeBlocks, TB>>>(row);
    scan1_kernel<<<SCAN_NB, SCAN_BLK>>>();
    scan2_kernel<<<1, 256>>>();
    scan3_kernel<<<SCAN_NB, SCAN_BLK>>>();
    scatter_kernel<<<edgeBlocks, TB>>>(row, col, vals);

    // Layer 1: h0 -> x1 (+h1)
    spmm_csr_kernel<true><<<rowWarpBlocks, TB>>>((const __half2*)h0P, x1P, h1P);
    // Layer 2: h1 -> x2 (fp32 only; layer 3 gathers fp32)
    spmm_csr_kernel<false><<<rowWarpBlocks, TB>>>((const __half2*)h1P, x2P,
                                                  nullptr);
    // Layer 3 (masked): x2 (fp32) -> x3, only rows consumed by scoring
    spmm_csr_masked_kernel<<<maskWarpBlocks, TB>>>(x2P, x3P);

    score_kernel<<<(BATCH * 32) / TB, TB>>>(user_emb, item_emb,
                                            users, pos_items, neg_items, out);
}